// round 5
// baseline (speedup 1.0000x reference)
#include <cuda_runtime.h>

// GaussianRP: x (8,16,32,1024) f32, log_sigma scalar f32
// out (8,16,1024,1024) f32:
//   rp[b,c,t,s] = exp(-max(|x_t|^2+|x_s|^2-2<x_t,x_s>, 0) / (2 sigma^2))
//
// Round 4: packed fp32 (fma.rn.f32x2) Gram kernel, cleaned. 128x128 output
// tile, 8x8 microtile per thread as 8x4 f32x2 accumulators. A-side smem tile
// stored element-duplicated so each 16B LDS yields two ready {a,a} packed
// operands; B-side packed pairs {b_j,b_j+1} are contiguous floats loaded as
// u64 directly (no mov.b64 repacking anywhere in the inner loop).
// Symmetric tile-pair scheme (36 of 64 pairs); each block stores its tile
// and the transpose.

#define NB   8
#define NC   16
#define NDIM 32
#define NT   1024
#define NBC  (NB * NC)

#define TILE  128
#define NTILE (NT / TILE)                  // 8
#define NPAIR (NTILE * (NTILE + 1) / 2)    // 36

typedef unsigned long long u64;

__device__ float g_sqnorm[NBC * NT];
__device__ float g_scale;   // 1/(2 sigma^2)

__device__ __forceinline__ float2 upk2(u64 v) {
    float2 f;
    asm("mov.b64 {%0, %1}, %2;" : "=f"(f.x), "=f"(f.y) : "l"(v));
    return f;
}
__device__ __forceinline__ u64 fma2(u64 a, u64 b, u64 c) {
    u64 d;
    asm("fma.rn.f32x2 %0, %1, %2, %3;" : "=l"(d) : "l"(a), "l"(b), "l"(c));
    return d;
}

__global__ __launch_bounds__(256)
void norms_kernel(const float* __restrict__ x,
                  const float* __restrict__ log_sigma) {
    int idx = blockIdx.x * blockDim.x + threadIdx.x;   // bc*NT + t
    if (idx == 0) g_scale = 0.5f * __expf(-2.f * log_sigma[0]);
    if (idx >= NBC * NT) return;
    int bc = idx >> 10;
    int t  = idx & (NT - 1);
    const float* p = x + (size_t)bc * NDIM * NT + t;
    float s = 0.f;
#pragma unroll
    for (int d = 0; d < NDIM; ++d) {
        float v = p[d * NT];
        s = fmaf(v, v, s);
    }
    g_sqnorm[idx] = s;
}

__global__ __launch_bounds__(256)
void gaussian_rp_kernel(const float* __restrict__ x,
                        float* __restrict__ out) {
    // A tile duplicated: At2[k][2*i] = At2[k][2*i+1] = x[k][t0+i]   (32 KB)
    // B tile plain:      As[k][j]    = x[k][s0+j]                    (16 KB)
    __shared__ __align__(16) float At2[NDIM][2 * TILE];
    __shared__ __align__(16) float As [NDIM][TILE];

    const int bc = blockIdx.x;
    const int p  = blockIdx.y;         // 0..NPAIR-1

    // triangular pair decode: p = ss*(ss+1)/2 + ts, ts <= ss
    int ss = 0;
#pragma unroll
    for (int c = 1; c < NTILE; ++c)
        ss += (p >= c * (c + 1) / 2) ? 1 : 0;
    const int ts = p - ss * (ss + 1) / 2;

    const int t0 = ts * TILE;
    const int s0 = ss * TILE;

    const int tx  = threadIdx.x;       // 0..15
    const int ty  = threadIdx.y;       // 0..15
    const int tid = ty * 16 + tx;      // 0..255

    // ---- load tiles: 32 rows x 128 cols each = 1024 float4 per side ----
    const float* xb = x + (size_t)bc * NDIM * NT;
#pragma unroll
    for (int r = 0; r < 4; ++r) {
        int lin = tid + 256 * r;       // 0..1023
        int d   = lin >> 5;            // k row
        int v   = lin & 31;            // float4 index within row
        float4 a = *(const float4*)(xb + d * NT + t0 + v * 4);
        float4 b = *(const float4*)(xb + d * NT + s0 + v * 4);
        *(float4*)&At2[d][v * 8]     = make_float4(a.x, a.x, a.y, a.y);
        *(float4*)&At2[d][v * 8 + 4] = make_float4(a.z, a.z, a.w, a.w);
        *(float4*)&As[d][v * 4] = b;
    }
    __syncthreads();

    // ---- 8x8 microtile as 8x4 packed accumulators ----
    // rows: i<4 -> t0 + ty*4 + i ; i>=4 -> t0 + 64 + ty*4 + (i-4)
    // cols: jp0 -> s0+tx*4+{0,1}, jp1 -> +{2,3}, jp2 -> s0+64+tx*4+{0,1}, jp3 -> +{2,3}
    u64 acc[8][4];
#pragma unroll
    for (int i = 0; i < 8; ++i)
#pragma unroll
        for (int j = 0; j < 4; ++j) acc[i][j] = 0ull;

#pragma unroll
    for (int k = 0; k < NDIM; ++k) {
        // duplicated A: 16B load = two packed {a,a} operands
        ulonglong2 a01 = *(const ulonglong2*)&At2[k][8 * ty];
        ulonglong2 a23 = *(const ulonglong2*)&At2[k][8 * ty + 4];
        ulonglong2 a45 = *(const ulonglong2*)&At2[k][128 + 8 * ty];
        ulonglong2 a67 = *(const ulonglong2*)&At2[k][128 + 8 * ty + 4];
        // plain B: contiguous float pair reinterpreted as packed operand
        ulonglong2 b01 = *(const ulonglong2*)&As[k][4 * tx];
        ulonglong2 b23 = *(const ulonglong2*)&As[k][64 + 4 * tx];

        u64 aa[8] = { a01.x, a01.y, a23.x, a23.y,
                      a45.x, a45.y, a67.x, a67.y };
        u64 bb[4] = { b01.x, b01.y, b23.x, b23.y };
#pragma unroll
        for (int i = 0; i < 8; ++i)
#pragma unroll
            for (int j = 0; j < 4; ++j)
                acc[i][j] = fma2(aa[i], bb[j], acc[i][j]);
    }

    // ---- epilogue: d2 -> exp ----
    const float scale = g_scale;
    const float* sq = &g_sqnorm[bc * NT];

    float nt[8], ns[8];
#pragma unroll
    for (int i = 0; i < 4; ++i) {
        nt[i]     = sq[t0 + ty * 4 + i];
        nt[i + 4] = sq[t0 + 64 + ty * 4 + i];
    }
#pragma unroll
    for (int j = 0; j < 4; ++j) {
        ns[j]     = sq[s0 + tx * 4 + j];
        ns[j + 4] = sq[s0 + 64 + tx * 4 + j];
    }

    float rp[8][8];
#pragma unroll
    for (int i = 0; i < 8; ++i)
#pragma unroll
        for (int jp = 0; jp < 4; ++jp) {
            float2 g = upk2(acc[i][jp]);
            int j0 = (jp < 2) ? jp * 2 : 4 + (jp - 2) * 2;
            float d2a = fmaxf(nt[i] + ns[j0]     - 2.f * g.x, 0.f);
            float d2b = fmaxf(nt[i] + ns[j0 + 1] - 2.f * g.y, 0.f);
            rp[i][j0]     = __expf(-d2a * scale);
            rp[i][j0 + 1] = __expf(-d2b * scale);
        }

    float* ob = out + (size_t)bc * NT * NT;

    // normal tile: rows t, cols s (float4 coalesced across tx)
#pragma unroll
    for (int i = 0; i < 8; ++i) {
        int t = t0 + ((i < 4) ? (ty * 4 + i) : (64 + ty * 4 + (i - 4)));
        *(float4*)(ob + (size_t)t * NT + s0 + 4 * tx) =
            make_float4(rp[i][0], rp[i][1], rp[i][2], rp[i][3]);
        *(float4*)(ob + (size_t)t * NT + s0 + 64 + 4 * tx) =
            make_float4(rp[i][4], rp[i][5], rp[i][6], rp[i][7]);
    }

    // transposed tile (skip on diagonal blocks): rows s, cols t
    if (ts != ss) {
#pragma unroll
        for (int j = 0; j < 8; ++j) {
            int s = s0 + ((j < 4) ? (tx * 4 + j) : (64 + tx * 4 + (j - 4)));
            *(float4*)(ob + (size_t)s * NT + t0 + 4 * ty) =
                make_float4(rp[0][j], rp[1][j], rp[2][j], rp[3][j]);
            *(float4*)(ob + (size_t)s * NT + t0 + 64 + 4 * ty) =
                make_float4(rp[4][j], rp[5][j], rp[6][j], rp[7][j]);
        }
    }
}

extern "C" void kernel_launch(void* const* d_in, const int* in_sizes, int n_in,
                              void* d_out, int out_size) {
    const float* x  = (const float*)d_in[0];
    const float* ls = (const float*)d_in[1];
    float* out      = (float*)d_out;

    norms_kernel<<<(NBC * NT + 255) / 256, 256>>>(x, ls);

    dim3 grid(NBC, NPAIR);
    dim3 block(16, 16);
    gaussian_rp_kernel<<<grid, block>>>(x, out);
}